// round 7
// baseline (speedup 1.0000x reference)
#include <cuda_runtime.h>

#define HH 512
#define WW 512
#define BB 2

// Packed row-pass result, one uint16 per pixel:
//   bit15 = mask (1 = fg), bits[0:15) = row distance to nearest OPPOSITE-class
//   pixel (0x7fff sentinel = none in this row; its squared value ~1.07e9 can
//   never beat any real candidate). 1 MB, L2-resident.
__device__ unsigned short g_pack16[BB * HH * WW];

// ---------------------------------------------------------------------------
// Kernel A: row pass via 512-bit row bitmask + ffs/clz word scans (R4 form).
// 1 row per block, 1 pixel per thread.
// ---------------------------------------------------------------------------
__global__ void __launch_bounds__(WW) row_pass(const float* __restrict__ gt) {
    const int b = blockIdx.x >> 9;          // blockIdx.x = b*512 + y
    const int y = blockIdx.x & 511;
    const int x = threadIdx.x;

    __shared__ unsigned int sw[WW / 32];    // 16 words = 512-bit row mask

    const float v = gt[((size_t)b * HH + y) * WW + x];
    const unsigned int m = (v == 1.0f) ? 1u : 0u;
    const unsigned int bits = __ballot_sync(0xFFFFFFFFu, m != 0u);
    if ((x & 31) == 0) sw[x >> 5] = bits;
    __syncthreads();

    const unsigned int xorm = m ? 0xFFFFFFFFu : 0u;  // opp(word) = word ^ xorm
    const int w0 = x >> 5, off = x & 31;
    const unsigned int cur = sw[w0] ^ xorm;

    int right = 0x7fff;
    {
        const unsigned int hi = cur & (0xFFFFFFFEu << off);
        if (hi) {
            right = (__ffs(hi) - 1) - off;
        } else {
            #pragma unroll 1
            for (int w = w0 + 1; w < WW / 32; ++w) {
                const unsigned int t = sw[w] ^ xorm;
                if (t) { right = (w << 5) + (__ffs(t) - 1) - x; break; }
            }
        }
    }
    int left = 0x7fff;
    {
        const unsigned int lo = cur & ((1u << off) - 1u);
        if (lo) {
            left = off - (31 - __clz(lo));
        } else {
            #pragma unroll 1
            for (int w = w0 - 1; w >= 0; --w) {
                const unsigned int t = sw[w] ^ xorm;
                if (t) { left = x - ((w << 5) + (31 - __clz(t))); break; }
            }
        }
    }

    const unsigned int d = (unsigned int)min(min(left, right), 0x7fff);
    g_pack16[((size_t)b * HH + y) * WW + x] = (unsigned short)(d | (m << 15));
}

// ---------------------------------------------------------------------------
// Kernel B: column pass with WARP-UNIFORM FIXED-TRIP scan (no data-dependent
// break in the load stream). After the center load, a warp max-reduce of
// best gives Rmax; the loop r=1..Rmax then has fully independent, clamped
// (branch-free) loads -> MLP collapses the former per-radius latency chain.
// Exact: including extra radii only adds valid candidates to the min;
// Rmax >= ceil(sqrt(best)) guarantees the exact window is covered.
// Opposite plane only; 2 px/thread per uint32; fused sqrt epilogue.
// ---------------------------------------------------------------------------
__global__ void __launch_bounds__(256) col_pass(float* __restrict__ out) {
    const int b = blockIdx.x >> 9;           // blockIdx.x = b*512 + i
    const int i = blockIdx.x & 511;
    const int t = threadIdx.x;

    const unsigned int* __restrict__ col =
        reinterpret_cast<const unsigned int*>(g_pack16) +
        (size_t)b * HH * (WW / 2) + t;

    const unsigned int u = col[i * (WW / 2)];
    const unsigned int mA = (u >> 15) & 1u;
    const unsigned int mB = (u >> 31) & 1u;
    const int roA = (int)(u & 0x7fffu);
    const int roB = (int)((u >> 16) & 0x7fffu);
    float bestA = (float)(roA * roA);
    float bestB = (float)(roB * roB);

    // Warp-uniform scan bound.
    float mb = fmaxf(bestA, bestB);
    #pragma unroll
    for (int o = 16; o; o >>= 1)
        mb = fmaxf(mb, __shfl_xor_sync(0xFFFFFFFFu, mb, o));
    const int Rmax = min(HH - 1, (int)sqrtf(mb) + 2);

    #pragma unroll 4
    for (int r = 1; r <= Rmax; ++r) {
        const float rr = (float)(r * r);
        const int up = i - r, dn = i + r;
        // Clamped, branch-free loads (independent across r -> full MLP).
        const unsigned int qu = col[max(up, 0) * (WW / 2)];
        const unsigned int qd = col[min(dn, HH - 1) * (WW / 2)];
        const float pu = (up >= 0) ? rr : 1e12f;   // OOB candidates disabled
        const float pd = (dn < HH) ? rr : 1e12f;

        const int rau = (int)(qu & 0x7fffu), rbu = (int)((qu >> 16) & 0x7fffu);
        const float fau = (((qu >> 15) & 1u) != mA) ? 0.0f : (float)(rau * rau);
        const float fbu = (((qu >> 31) & 1u) != mB) ? 0.0f : (float)(rbu * rbu);
        bestA = fminf(bestA, fau + pu);
        bestB = fminf(bestB, fbu + pu);

        const int rad = (int)(qd & 0x7fffu), rbd = (int)((qd >> 16) & 0x7fffu);
        const float fad = (((qd >> 15) & 1u) != mA) ? 0.0f : (float)(rad * rad);
        const float fbd = (((qd >> 31) & 1u) != mB) ? 0.0f : (float)(rbd * rbd);
        bestA = fminf(bestA, fad + pd);
        bestB = fminf(bestB, fbd + pd);
    }

    float2 o;
    o.x = (mA ? -1.0f : 1.0f) * sqrtf(bestA);
    o.y = (mB ? -1.0f : 1.0f) * sqrtf(bestB);
    reinterpret_cast<float2*>(out + ((size_t)b * HH + i) * WW)[t] = o;
}

extern "C" void kernel_launch(void* const* d_in, const int* in_sizes, int n_in,
                              void* d_out, int out_size) {
    const float* gt = (const float*)d_in[0];
    float* out = (float*)d_out;
    (void)in_sizes; (void)n_in; (void)out_size;

    row_pass<<<BB * HH, WW>>>(gt);
    col_pass<<<BB * HH, 256>>>(out);
}

// round 8
// speedup vs baseline: 1.2090x; 1.2090x over previous
#include <cuda_runtime.h>

#define HH 512
#define WW 512
#define BB 2
#define NP 256          // uint32 pixel-pairs per row
#define PAIRS 8         // pairs per col-pass block

// Packed row-pass result, one uint16 per pixel:
//   bit15 = mask (1 = fg), bits[0:15) = row distance to nearest OPPOSITE-class
//   pixel (0x7fff sentinel = none in this row; its squared value can never
//   beat any real candidate). 1 MB, L2-resident.
__device__ unsigned short g_pack16[BB * HH * WW];

// ---------------------------------------------------------------------------
// Kernel A: row pass via 512-bit row bitmask + ffs/clz word scans (best
// measured form, R4). 1 row per block, 1 pixel per thread.
// ---------------------------------------------------------------------------
__global__ void __launch_bounds__(WW) row_pass(const float* __restrict__ gt) {
    const int b = blockIdx.x >> 9;          // blockIdx.x = b*512 + y
    const int y = blockIdx.x & 511;
    const int x = threadIdx.x;

    __shared__ unsigned int sw[WW / 32];    // 16 words = 512-bit row mask

    const float v = gt[((size_t)b * HH + y) * WW + x];
    const unsigned int m = (v == 1.0f) ? 1u : 0u;
    const unsigned int bits = __ballot_sync(0xFFFFFFFFu, m != 0u);
    if ((x & 31) == 0) sw[x >> 5] = bits;
    __syncthreads();

    const unsigned int xorm = m ? 0xFFFFFFFFu : 0u;  // opp(word) = word ^ xorm
    const int w0 = x >> 5, off = x & 31;
    const unsigned int cur = sw[w0] ^ xorm;

    int right = 0x7fff;
    {
        const unsigned int hi = cur & (0xFFFFFFFEu << off);
        if (hi) {
            right = (__ffs(hi) - 1) - off;
        } else {
            #pragma unroll 1
            for (int w = w0 + 1; w < WW / 32; ++w) {
                const unsigned int t = sw[w] ^ xorm;
                if (t) { right = (w << 5) + (__ffs(t) - 1) - x; break; }
            }
        }
    }
    int left = 0x7fff;
    {
        const unsigned int lo = cur & ((1u << off) - 1u);
        if (lo) {
            left = off - (31 - __clz(lo));
        } else {
            #pragma unroll 1
            for (int w = w0 - 1; w >= 0; --w) {
                const unsigned int t = sw[w] ^ xorm;
                if (t) { left = x - ((w << 5) + (31 - __clz(t))); break; }
            }
        }
    }

    const unsigned int d = (unsigned int)min(min(left, right), 0x7fff);
    g_pack16[((size_t)b * HH + y) * WW + x] = (unsigned short)(d | (m << 15));
}

// ---------------------------------------------------------------------------
// Kernel B: column pass with FULL-COLUMN shared staging.
// Block = 8 pixel-pairs (16 columns) x all 512 rows (16 KB smem), 1024 thr.
// Staging: 4 independent loads/thread, warp covers 4 rows x 8 pairs
//   (4 x 32B sectors, fully coalesced at sector granularity).
// Scan: 4 pixel-pairs per thread, exact adaptive window (stop when
//   r^2 >= best; provably exact) against LDS (~35 cyc/step vs ~260 L2).
//   Layout s[row*8 + pair] -> warp accesses 32 consecutive words: no
//   bank conflicts. Opposite plane only; fused sqrt epilogue.
// ---------------------------------------------------------------------------
__global__ void __launch_bounds__(1024) col_pass(float* __restrict__ out) {
    const int b = blockIdx.x >> 5;          // blockIdx.x = b*32 + tile
    const int pairbase = (blockIdx.x & 31) * PAIRS;
    const int t = threadIdx.x;

    __shared__ unsigned int sw[HH * PAIRS]; // [row][pair], 16 KB

    const unsigned int* __restrict__ pk =
        reinterpret_cast<const unsigned int*>(g_pack16) + (size_t)b * HH * NP;

    // Stage: idx = it*1024 + t -> (row = idx>>3, p = idx&7).
    #pragma unroll
    for (int it = 0; it < 4; ++it) {
        const int idx = it * 1024 + t;
        const int row = idx >> 3;
        const int p = idx & 7;
        sw[idx] = pk[row * NP + pairbase + p];
    }
    __syncthreads();

    // Scan: same (row, p) mapping, 4 pixel-pairs per thread.
    #pragma unroll 1
    for (int it = 0; it < 4; ++it) {
        const int idx = it * 1024 + t;
        const int row = idx >> 3;
        const int p = idx & 7;

        const unsigned int u = sw[idx];
        const unsigned int mA = (u >> 15) & 1u;
        const unsigned int mB = (u >> 31) & 1u;
        const int roA = (int)(u & 0x7fffu);
        const int roB = (int)((u >> 16) & 0x7fffu);
        float bestA = (float)(roA * roA);
        float bestB = (float)(roB * roB);

        #pragma unroll 1
        for (int r = 1; r < HH; ++r) {
            const float rr = (float)(r * r);
            if (rr >= bestA && rr >= bestB) break;
            const int up = row - r, dn = row + r;
            if (up >= 0) {
                const unsigned int q = sw[up * PAIRS + p];
                const int ra = (int)(q & 0x7fffu), rb = (int)((q >> 16) & 0x7fffu);
                const float fa = (((q >> 15) & 1u) != mA) ? 0.0f : (float)(ra * ra);
                const float fb = (((q >> 31) & 1u) != mB) ? 0.0f : (float)(rb * rb);
                bestA = fminf(bestA, fa + rr);
                bestB = fminf(bestB, fb + rr);
            }
            if (dn < HH) {
                const unsigned int q = sw[dn * PAIRS + p];
                const int ra = (int)(q & 0x7fffu), rb = (int)((q >> 16) & 0x7fffu);
                const float fa = (((q >> 15) & 1u) != mA) ? 0.0f : (float)(ra * ra);
                const float fb = (((q >> 31) & 1u) != mB) ? 0.0f : (float)(rb * rb);
                bestA = fminf(bestA, fa + rr);
                bestB = fminf(bestB, fb + rr);
            }
        }

        float2 o;
        o.x = (mA ? -1.0f : 1.0f) * sqrtf(bestA);
        o.y = (mB ? -1.0f : 1.0f) * sqrtf(bestB);
        reinterpret_cast<float2*>(out)[(size_t)b * HH * NP + row * NP + pairbase + p] = o;
    }
}

extern "C" void kernel_launch(void* const* d_in, const int* in_sizes, int n_in,
                              void* d_out, int out_size) {
    const float* gt = (const float*)d_in[0];
    float* out = (float*)d_out;
    (void)in_sizes; (void)n_in; (void)out_size;

    row_pass<<<BB * HH, WW>>>(gt);
    col_pass<<<BB * (NP / PAIRS), 1024>>>(out);
}